// round 14
// baseline (speedup 1.0000x reference)
#include <cuda_runtime.h>
#include <cuda_fp16.h>
#include <cstdint>
#include <math.h>

// Problem dims
#define T_DIM 1024
#define B_DIM 32
#define C_DIM 1024
#define K_DIM 1024
#define E_DIM 16
#define TBC   33554432  // T*B*C

// ---------------- device scratch (allocation-free rule: __device__ globals) -----
__device__ float                   g_resp[B_DIM * E_DIM];
__device__ int                     g_flag = 0;   // routing-done counter (reset each run)
__device__ int                     g_done = 0;   // wgen-finished counter (reset each run)
__device__ __align__(256) __half   g_w[(size_t)B_DIM * C_DIM * C_DIM];  // 67MB

// ---------------- helpers -------------------------------------------------------
__device__ __forceinline__ uint32_t smem_u32(const void* p) {
    uint32_t a;
    asm("{ .reg .u64 t; cvta.to.shared.u64 t, %1; cvt.u32.u64 %0, t; }" : "=r"(a) : "l"(p));
    return a;
}
__device__ __forceinline__ void cp16(uint32_t dst, const void* src) {
    asm volatile("cp.async.cg.shared.global [%0], [%1], 16;" :: "r"(dst), "l"(src));
}
__device__ __forceinline__ void ldsm_x4(uint32_t* r, uint32_t addr) {
    asm volatile("ldmatrix.sync.aligned.m8n8.x4.shared.b16 {%0,%1,%2,%3}, [%4];"
                 : "=r"(r[0]), "=r"(r[1]), "=r"(r[2]), "=r"(r[3]) : "r"(addr));
}
// fp16 in, fp16 accum
__device__ __forceinline__ void mma16816_h(uint32_t* c, const uint32_t* a, const uint32_t* b) {
    asm volatile(
        "mma.sync.aligned.m16n8k16.row.col.f16.f16.f16.f16 "
        "{%0,%1}, {%2,%3,%4,%5}, {%6,%7}, {%0,%1};"
        : "+r"(c[0]), "+r"(c[1])
        : "r"(a[0]), "r"(a[1]), "r"(a[2]), "r"(a[3]), "r"(b[0]), "r"(b[1]));
}

// ================================================================================
// Kernel 1 (fused): blocks 0..31 compute routing for b=blockIdx first, publish
// g_resp and bump g_flag. ALL 1024 blocks: issue pw loads, spin on flag (hidden
// under loads), mix W[b] = sum_e resp[b,e]*pw[e]; block 0 emits the loss scalar.
// Last finishing block resets flags for graph-replay determinism.
// ================================================================================
__global__ void __launch_bounds__(256)
wgen_kernel(const float4* __restrict__ pw,
            const float* __restrict__ key,
            const float* __restrict__ aw,
            const float* __restrict__ ab,
            float* __restrict__ out, int out_size) {
    __shared__ float sresp[B_DIM * E_DIM];
    __shared__ float slog[E_DIM];
    const int tid = threadIdx.x;
    const int bid = blockIdx.x;

    // ---- Phase A: routing (blocks 0..31 only) ----
    if (bid < B_DIM) {
        const int e = tid >> 4;          // 16 threads per expert
        const int l = tid & 15;
        const float* kr = key + bid * K_DIM;
        float acc = 0.f;
        #pragma unroll 8
        for (int k = l; k < K_DIM; k += 16)
            acc = fmaf(kr[k], aw[k * E_DIM + e], acc);
        #pragma unroll
        for (int off = 8; off > 0; off >>= 1)
            acc += __shfl_xor_sync(0xFFFFFFFF, acc, off);
        if (l == 0) slog[e] = acc + ab[e];
        __syncthreads();
        if (tid == 0) {
            float mx = -1e30f;
            #pragma unroll
            for (int j = 0; j < E_DIM; j++) mx = fmaxf(mx, slog[j]);
            float v[E_DIM]; float s = 0.f;
            #pragma unroll
            for (int j = 0; j < E_DIM; j++) { v[j] = expf(slog[j] - mx); s += v[j]; }
            float inv = 1.f / s;
            #pragma unroll
            for (int j = 0; j < E_DIM; j++) g_resp[bid * E_DIM + j] = v[j] * inv;
            __threadfence();
            atomicAdd(&g_flag, 1);
        }
    }

    // ---- Phase B: all blocks — pw loads first (hide the flag wait) ----
    size_t n4 = (size_t)bid * 256 + tid;  // < 262144 (= C*C/4)
    float4 p[E_DIM];
    #pragma unroll
    for (int e = 0; e < E_DIM; e++) p[e] = pw[(size_t)e * 262144 + n4];

    if (tid == 0) {
        while (atomicAdd(&g_flag, 0) < B_DIM) { }
        __threadfence();
    }
    __syncthreads();
    for (int i = tid; i < B_DIM * E_DIM; i += 256)
        sresp[i] = g_resp[i];
    __syncthreads();

    if (bid == 0 && tid == 0 && out_size > TBC) {
        float imp[E_DIM]; float tot = 0.f;
        #pragma unroll
        for (int j = 0; j < E_DIM; j++) {
            float s = 0.f;
            for (int bb = 0; bb < B_DIM; bb++) s += sresp[bb * E_DIM + j];
            imp[j] = s; tot += s;
        }
        float mean = tot / E_DIM;
        float var = 0.f;
        #pragma unroll
        for (int j = 0; j < E_DIM; j++) { float d = imp[j] - mean; var += d * d; }
        var /= (E_DIM - 1);
        out[out_size - 1] = 0.01f * sqrtf(var) / mean;
    }

    for (int b = 0; b < B_DIM; b++) {
        float rx = 0.f, ry = 0.f, rz = 0.f, rw = 0.f;
        #pragma unroll
        for (int e = 0; e < E_DIM; e++) {
            float r = sresp[b * E_DIM + e];
            rx = fmaf(r, p[e].x, rx);
            ry = fmaf(r, p[e].y, ry);
            rz = fmaf(r, p[e].z, rz);
            rw = fmaf(r, p[e].w, rw);
        }
        union { __half h[4]; uint2 u; } o;
        o.h[0] = __float2half(rx);
        o.h[1] = __float2half(ry);
        o.h[2] = __float2half(rz);
        o.h[3] = __float2half(rw);
        ((uint2*)(g_w + (size_t)b * (C_DIM * C_DIM)))[n4] = o.u;
    }

    // ---- reset flags for the next graph replay (last block to finish) ----
    __syncthreads();
    if (tid == 0) {
        __threadfence();
        int d = atomicAdd(&g_done, 1);
        if (d == (int)gridDim.x - 1) { g_flag = 0; g_done = 0; __threadfence(); }
    }
}

// ================================================================================
// Kernel 2: batched GEMM  Y_b = X_b @ W_b^T + residual  (mma.sync fp16, fp16 acc)
//   A: fp32 LDG.128 -> regs -> cvt -> STS fp16 (double-buffered; convert hidden
//   under MMA phase). B: fp16 cp.async 2-stage. CTA 128x256, warp tile 64x64.
//   Per iter: wait -> sync -> LDG A(kc+1) + cp B(kc+1) -> MMA(kc) -> STS A(kc+1)
// ================================================================================
#define BM 128
#define BN 256
#define BK 32
#define PROW 80                         // 32 fp16 = 64B + 16B pad
#define NKC (C_DIM / BK)                // 32 k-chunks
#define A_STAGE (BM * PROW)             // 10240
#define B_STAGE (BN * PROW)             // 20480
#define SMEM_BYTES (2 * (A_STAGE + B_STAGE))  // 61440

__device__ __forceinline__ void issue_B(uint32_t bbuf, const __half* Bg, int ko, int tid) {
    #pragma unroll
    for (int i = 0; i < 4; i++) {
        int idx = tid + i * 256;
        int r = idx >> 2, c = idx & 3;
        cp16(bbuf + r * PROW + c * 16, Bg + (size_t)r * C_DIM + ko + c * 8);
    }
}
__device__ __forceinline__ void loadA_regs(float4* v, const float* Agf, int ko, int tid) {
    #pragma unroll
    for (int i = 0; i < 4; i++) {
        int idx = tid + i * 256;
        int r = idx >> 3, c = idx & 7;
        v[i] = *(const float4*)(Agf + (size_t)r * (B_DIM * C_DIM) + ko + c * 4);
    }
}
__device__ __forceinline__ void stsA(char* abuf, const float4* v, int tid) {
    #pragma unroll
    for (int i = 0; i < 4; i++) {
        int idx = tid + i * 256;
        int r = idx >> 3, c = idx & 7;
        union { __half h[4]; uint2 u; } o;
        o.h[0] = __float2half(v[i].x);
        o.h[1] = __float2half(v[i].y);
        o.h[2] = __float2half(v[i].z);
        o.h[3] = __float2half(v[i].w);
        *(uint2*)(abuf + r * PROW + c * 8) = o.u;
    }
}

__global__ void __launch_bounds__(256, 2)
gemm_kernel(const float* __restrict__ x, float* __restrict__ out) {
    extern __shared__ __align__(16) char smem[];

    const int tid = threadIdx.x;
    const int lane = tid & 31, wid = tid >> 5;
    const int wm = wid >> 2;          // 0..1  (64 rows each)
    const int wn = wid & 3;           // 0..3  (64 cols each)
    const int o0 = blockIdx.x * BN;
    const int t0 = blockIdx.y * BM;
    const int b  = blockIdx.z;

    const float*  Agf = x   + ((size_t)t0 * B_DIM + b) * C_DIM;      // fp32 A source
    const __half* Bg  = g_w + ((size_t)b * C_DIM + o0) * C_DIM;      // row stride C

    const uint32_t base = smem_u32(smem);
    char*    aPtr[2] = { smem, smem + A_STAGE };
    uint32_t aAdr[2] = { base, base + A_STAGE };
    uint32_t bAdr[2] = { base + 2 * A_STAGE, base + 2 * A_STAGE + B_STAGE };

    uint32_t acc[4][8][2];            // fp16x2 accumulators, warp tile 64x64
    #pragma unroll
    for (int i = 0; i < 4; i++)
        #pragma unroll
        for (int j = 0; j < 8; j++) { acc[i][j][0] = 0u; acc[i][j][1] = 0u; }

    // ldmatrix address components
    const int a_row = lane & 15;
    const int a_col = (lane >> 4) * 8;
    const int bq = lane >> 3;
    const int b_row = (bq >> 1) * 8 + (lane & 7);
    const int b_col = (bq & 1) * 8;

    // prologue: chunk 0 — A via regs, B via cp.async
    float4 areg[4];
    loadA_regs(areg, Agf, 0, tid);
    issue_B(bAdr[0], Bg, 0, tid);
    asm volatile("cp.async.commit_group;" ::: "memory");
    stsA(aPtr[0], areg, tid);

    #pragma unroll 1
    for (int kc = 0; kc < NKC; kc++) {
        const int cur = kc & 1, nxt = cur ^ 1;
        asm volatile("cp.async.wait_group 0;" ::: "memory");  // B[cur] landed
        __syncthreads();               // A16[cur] visible; prev readers done

        if (kc + 1 < NKC) {            // stage kc+1 (LDG latency hidden by MMA)
            loadA_regs(areg, Agf, (kc + 1) * BK, tid);
            issue_B(bAdr[nxt], Bg, (kc + 1) * BK, tid);
            asm volatile("cp.async.commit_group;" ::: "memory");
        }

        const uint32_t Ab = aAdr[cur] + (uint32_t)(wm * 64) * PROW;
        const uint32_t Bb = bAdr[cur] + (uint32_t)(wn * 64) * PROW;

        #pragma unroll
        for (int ks = 0; ks < 2; ks++) {
            uint32_t af[4][4];
            #pragma unroll
            for (int mt = 0; mt < 4; mt++)
                ldsm_x4(af[mt], Ab + (uint32_t)(mt * 16 + a_row) * PROW + (a_col + ks * 16) * 2);
            uint32_t bf[8][2];
            #pragma unroll
            for (int nt2 = 0; nt2 < 4; nt2++) {
                uint32_t t4[4];
                ldsm_x4(t4, Bb + (uint32_t)(nt2 * 16 + b_row) * PROW + (b_col + ks * 16) * 2);
                bf[nt2 * 2][0] = t4[0]; bf[nt2 * 2][1] = t4[1];
                bf[nt2 * 2 + 1][0] = t4[2]; bf[nt2 * 2 + 1][1] = t4[3];
            }
            #pragma unroll
            for (int mt = 0; mt < 4; mt++)
                #pragma unroll
                for (int nt = 0; nt < 8; nt++)
                    mma16816_h(acc[mt][nt], af[mt], bf[nt]);
        }

        if (kc + 1 < NKC)
            stsA(aPtr[nxt], areg, tid);   // convert+store staged A (regs ready)
    }

    // epilogue: fused residual add, fp32 out
    const int erow = lane >> 2;
    const int ecol = (lane & 3) * 2;
    #pragma unroll
    for (int mt = 0; mt < 4; mt++) {
        int t_lo = t0 + wm * 64 + mt * 16 + erow;
        #pragma unroll
        for (int nt = 0; nt < 8; nt++) {
            int o = o0 + wn * 64 + nt * 8 + ecol;
            size_t i0 = ((size_t)t_lo * B_DIM + b) * C_DIM + o;
            size_t i1 = i0 + (size_t)8 * B_DIM * C_DIM;   // t_lo + 8
            float2 y0 = __half22float2(*(const __half2*)&acc[mt][nt][0]);
            float2 y1 = __half22float2(*(const __half2*)&acc[mt][nt][1]);
            float2 x0 = *(const float2*)(x + i0);
            float2 x1 = *(const float2*)(x + i1);
            y0.x += x0.x; y0.y += x0.y;
            y1.x += x1.x; y1.y += x1.y;
            *(float2*)(out + i0) = y0;
            *(float2*)(out + i1) = y1;
        }
    }
}

// ================================================================================
extern "C" void kernel_launch(void* const* d_in, const int* in_sizes, int n_in,
                              void* d_out, int out_size) {
    const float* x   = (const float*)d_in[0];
    const float* key = (const float*)d_in[1];
    const float* aw  = (const float*)d_in[2];
    const float* ab  = (const float*)d_in[3];
    const float* pw  = (const float*)d_in[4];
    float* out = (float*)d_out;

    cudaFuncSetAttribute(gemm_kernel, cudaFuncAttributeMaxDynamicSharedMemorySize, SMEM_BYTES);

    wgen_kernel<<<1024, 256>>>((const float4*)pw, key, aw, ab, out, out_size);
    gemm_kernel<<<dim3(C_DIM / BN, T_DIM / BM, B_DIM), 256, SMEM_BYTES>>>(x, out);
}

// round 15
// speedup vs baseline: 1.0578x; 1.0578x over previous
#include <cuda_runtime.h>
#include <cuda_fp16.h>
#include <cstdint>
#include <math.h>

// Problem dims
#define T_DIM 1024
#define B_DIM 32
#define C_DIM 1024
#define K_DIM 1024
#define E_DIM 16
#define TBC   33554432  // T*B*C

// ---------------- device scratch (allocation-free rule: __device__ globals) -----
__device__ float                   g_resp[B_DIM * E_DIM];
__device__ __align__(256) __half   g_w[(size_t)B_DIM * C_DIM * C_DIM];  // 67MB

// ---------------- helpers -------------------------------------------------------
__device__ __forceinline__ uint32_t smem_u32(const void* p) {
    uint32_t a;
    asm("{ .reg .u64 t; cvta.to.shared.u64 t, %1; cvt.u32.u64 %0, t; }" : "=r"(a) : "l"(p));
    return a;
}
__device__ __forceinline__ void cp16(uint32_t dst, const void* src) {
    asm volatile("cp.async.cg.shared.global [%0], [%1], 16;" :: "r"(dst), "l"(src));
}
__device__ __forceinline__ void ldsm_x4(uint32_t* r, uint32_t addr) {
    asm volatile("ldmatrix.sync.aligned.m8n8.x4.shared.b16 {%0,%1,%2,%3}, [%4];"
                 : "=r"(r[0]), "=r"(r[1]), "=r"(r[2]), "=r"(r[3]) : "r"(addr));
}
// fp16 in, fp16 accum
__device__ __forceinline__ void mma16816_h(uint32_t* c, const uint32_t* a, const uint32_t* b) {
    asm volatile(
        "mma.sync.aligned.m16n8k16.row.col.f16.f16.f16.f16 "
        "{%0,%1}, {%2,%3,%4,%5}, {%6,%7}, {%0,%1};"
        : "+r"(c[0]), "+r"(c[1])
        : "r"(a[0]), "r"(a[1]), "r"(a[2]), "r"(a[3]), "r"(b[0]), "r"(b[1]));
}

// ================================================================================
// Kernel 1: routing — one block per batch element; warp w computes logit (b, e=w)
// ================================================================================
__global__ void __launch_bounds__(512)
routing_kernel(const float* __restrict__ key,
               const float* __restrict__ aw,
               const float* __restrict__ ab) {
    __shared__ float slog[E_DIM];
    const int b = blockIdx.x;
    const int lane = threadIdx.x & 31;
    const int e = threadIdx.x >> 5;          // 16 warps = 16 experts
    const float* kr = key + b * K_DIM;

    float a0 = 0.f, a1 = 0.f, a2 = 0.f, a3 = 0.f;   // 4 indep chains
    #pragma unroll
    for (int j = 0; j < 8; j += 4) {
        a0 = fmaf(kr[lane + (j + 0) * 32], aw[(lane + (j + 0) * 32) * E_DIM + e], a0);
        a1 = fmaf(kr[lane + (j + 1) * 32], aw[(lane + (j + 1) * 32) * E_DIM + e], a1);
        a2 = fmaf(kr[lane + (j + 2) * 32], aw[(lane + (j + 2) * 32) * E_DIM + e], a2);
        a3 = fmaf(kr[lane + (j + 3) * 32], aw[(lane + (j + 3) * 32) * E_DIM + e], a3);
    }
    #pragma unroll
    for (int j = 8; j < 32; j += 4) {
        a0 = fmaf(kr[lane + (j + 0) * 32], aw[(lane + (j + 0) * 32) * E_DIM + e], a0);
        a1 = fmaf(kr[lane + (j + 1) * 32], aw[(lane + (j + 1) * 32) * E_DIM + e], a1);
        a2 = fmaf(kr[lane + (j + 2) * 32], aw[(lane + (j + 2) * 32) * E_DIM + e], a2);
        a3 = fmaf(kr[lane + (j + 3) * 32], aw[(lane + (j + 3) * 32) * E_DIM + e], a3);
    }
    float acc = (a0 + a1) + (a2 + a3);
    #pragma unroll
    for (int off = 16; off > 0; off >>= 1)
        acc += __shfl_xor_sync(0xFFFFFFFF, acc, off);
    if (lane == 0) slog[e] = acc + ab[e];
    __syncthreads();

    if (threadIdx.x == 0) {
        float mx = -1e30f;
        #pragma unroll
        for (int j = 0; j < E_DIM; j++) mx = fmaxf(mx, slog[j]);
        float v[E_DIM]; float s = 0.f;
        #pragma unroll
        for (int j = 0; j < E_DIM; j++) { v[j] = expf(slog[j] - mx); s += v[j]; }
        float inv = 1.f / s;
        #pragma unroll
        for (int j = 0; j < E_DIM; j++) g_resp[b * E_DIM + j] = v[j] * inv;
    }
}

// ================================================================================
// Kernel 2: W[b] = sum_e resp[b,e] * pw_w1[e] in HALF2 arithmetic (fp16 out);
//           block 0 emits the loss scalar (fp32, exact).
// ================================================================================
__global__ void __launch_bounds__(256)
wgen_kernel(const float4* __restrict__ pw,
            float* __restrict__ out, int out_size) {
    __shared__ __half2 sresp2[B_DIM * E_DIM];      // (r,r) broadcast pairs
    __shared__ float   srespf[B_DIM * E_DIM];
    for (int i = threadIdx.x; i < B_DIM * E_DIM; i += blockDim.x) {
        float r = g_resp[i];
        srespf[i] = r;
        sresp2[i] = __float2half2_rn(r);
    }
    __syncthreads();

    if (blockIdx.x == 0 && threadIdx.x == 0 && out_size > TBC) {
        float imp[E_DIM]; float tot = 0.f;
        #pragma unroll
        for (int j = 0; j < E_DIM; j++) {
            float s = 0.f;
            for (int bb = 0; bb < B_DIM; bb++) s += srespf[bb * E_DIM + j];
            imp[j] = s; tot += s;
        }
        float mean = tot / E_DIM;
        float var = 0.f;
        #pragma unroll
        for (int j = 0; j < E_DIM; j++) { float d = imp[j] - mean; var += d * d; }
        var /= (E_DIM - 1);
        out[out_size - 1] = 0.01f * sqrtf(var) / mean;
    }

    size_t n4 = (size_t)blockIdx.x * blockDim.x + threadIdx.x;  // < 262144 (= C*C/4)
    __half2 p2[2 * E_DIM];                      // pw quad as half2 pairs (32 regs)
    #pragma unroll
    for (int e = 0; e < E_DIM; e++) {
        float4 v = pw[(size_t)e * 262144 + n4];
        p2[2 * e]     = __floats2half2_rn(v.x, v.y);
        p2[2 * e + 1] = __floats2half2_rn(v.z, v.w);
    }
    for (int b = 0; b < B_DIM; b++) {
        __half2 a0 = __float2half2_rn(0.f);
        __half2 a1 = __float2half2_rn(0.f);
        #pragma unroll
        for (int e = 0; e < E_DIM; e++) {
            __half2 r = sresp2[b * E_DIM + e];
            a0 = __hfma2(r, p2[2 * e],     a0);
            a1 = __hfma2(r, p2[2 * e + 1], a1);
        }
        union { __half2 h[2]; uint2 u; } o;
        o.h[0] = a0; o.h[1] = a1;
        ((uint2*)(g_w + (size_t)b * (C_DIM * C_DIM)))[n4] = o.u;
    }
}

// ================================================================================
// Kernel 3: batched GEMM  Y_b = X_b @ W_b^T + residual  (mma.sync fp16, fp16 acc)
//   A: fp32 LDG.128 -> regs -> cvt -> STS fp16 (double-buffered; convert hidden
//   under MMA phase). B: fp16 cp.async 2-stage. CTA 128x256, warp tile 64x64.
//   Per iter: wait -> sync -> LDG A(kc+1) + cp B(kc+1) -> MMA(kc) -> STS A(kc+1)
// ================================================================================
#define BM 128
#define BN 256
#define BK 32
#define PROW 80                         // 32 fp16 = 64B + 16B pad
#define NKC (C_DIM / BK)                // 32 k-chunks
#define A_STAGE (BM * PROW)             // 10240
#define B_STAGE (BN * PROW)             // 20480
#define SMEM_BYTES (2 * (A_STAGE + B_STAGE))  // 61440

__device__ __forceinline__ void issue_B(uint32_t bbuf, const __half* Bg, int ko, int tid) {
    #pragma unroll
    for (int i = 0; i < 4; i++) {
        int idx = tid + i * 256;
        int r = idx >> 2, c = idx & 3;
        cp16(bbuf + r * PROW + c * 16, Bg + (size_t)r * C_DIM + ko + c * 8);
    }
}
__device__ __forceinline__ void loadA_regs(float4* v, const float* Agf, int ko, int tid) {
    #pragma unroll
    for (int i = 0; i < 4; i++) {
        int idx = tid + i * 256;
        int r = idx >> 3, c = idx & 7;
        v[i] = *(const float4*)(Agf + (size_t)r * (B_DIM * C_DIM) + ko + c * 4);
    }
}
__device__ __forceinline__ void stsA(char* abuf, const float4* v, int tid) {
    #pragma unroll
    for (int i = 0; i < 4; i++) {
        int idx = tid + i * 256;
        int r = idx >> 3, c = idx & 7;
        union { __half h[4]; uint2 u; } o;
        o.h[0] = __float2half(v[i].x);
        o.h[1] = __float2half(v[i].y);
        o.h[2] = __float2half(v[i].z);
        o.h[3] = __float2half(v[i].w);
        *(uint2*)(abuf + r * PROW + c * 8) = o.u;
    }
}

__global__ void __launch_bounds__(256, 2)
gemm_kernel(const float* __restrict__ x, float* __restrict__ out) {
    extern __shared__ __align__(16) char smem[];

    const int tid = threadIdx.x;
    const int lane = tid & 31, wid = tid >> 5;
    const int wm = wid >> 2;          // 0..1  (64 rows each)
    const int wn = wid & 3;           // 0..3  (64 cols each)
    const int o0 = blockIdx.x * BN;
    const int t0 = blockIdx.y * BM;
    const int b  = blockIdx.z;

    const float*  Agf = x   + ((size_t)t0 * B_DIM + b) * C_DIM;      // fp32 A source
    const __half* Bg  = g_w + ((size_t)b * C_DIM + o0) * C_DIM;      // row stride C

    const uint32_t base = smem_u32(smem);
    char*    aPtr[2] = { smem, smem + A_STAGE };
    uint32_t aAdr[2] = { base, base + A_STAGE };
    uint32_t bAdr[2] = { base + 2 * A_STAGE, base + 2 * A_STAGE + B_STAGE };

    uint32_t acc[4][8][2];            // fp16x2 accumulators, warp tile 64x64
    #pragma unroll
    for (int i = 0; i < 4; i++)
        #pragma unroll
        for (int j = 0; j < 8; j++) { acc[i][j][0] = 0u; acc[i][j][1] = 0u; }

    // ldmatrix address components
    const int a_row = lane & 15;
    const int a_col = (lane >> 4) * 8;
    const int bq = lane >> 3;
    const int b_row = (bq >> 1) * 8 + (lane & 7);
    const int b_col = (bq & 1) * 8;

    // prologue: chunk 0 — A via regs, B via cp.async
    float4 areg[4];
    loadA_regs(areg, Agf, 0, tid);
    issue_B(bAdr[0], Bg, 0, tid);
    asm volatile("cp.async.commit_group;" ::: "memory");
    stsA(aPtr[0], areg, tid);

    #pragma unroll 1
    for (int kc = 0; kc < NKC; kc++) {
        const int cur = kc & 1, nxt = cur ^ 1;
        asm volatile("cp.async.wait_group 0;" ::: "memory");  // B[cur] landed
        __syncthreads();               // A16[cur] visible; prev readers done

        if (kc + 1 < NKC) {            // stage kc+1 (LDG latency hidden by MMA)
            loadA_regs(areg, Agf, (kc + 1) * BK, tid);
            issue_B(bAdr[nxt], Bg, (kc + 1) * BK, tid);
            asm volatile("cp.async.commit_group;" ::: "memory");
        }

        const uint32_t Ab = aAdr[cur] + (uint32_t)(wm * 64) * PROW;
        const uint32_t Bb = bAdr[cur] + (uint32_t)(wn * 64) * PROW;

        #pragma unroll
        for (int ks = 0; ks < 2; ks++) {
            uint32_t af[4][4];
            #pragma unroll
            for (int mt = 0; mt < 4; mt++)
                ldsm_x4(af[mt], Ab + (uint32_t)(mt * 16 + a_row) * PROW + (a_col + ks * 16) * 2);
            uint32_t bf[8][2];
            #pragma unroll
            for (int nt2 = 0; nt2 < 4; nt2++) {
                uint32_t t4[4];
                ldsm_x4(t4, Bb + (uint32_t)(nt2 * 16 + b_row) * PROW + (b_col + ks * 16) * 2);
                bf[nt2 * 2][0] = t4[0]; bf[nt2 * 2][1] = t4[1];
                bf[nt2 * 2 + 1][0] = t4[2]; bf[nt2 * 2 + 1][1] = t4[3];
            }
            #pragma unroll
            for (int mt = 0; mt < 4; mt++)
                #pragma unroll
                for (int nt = 0; nt < 8; nt++)
                    mma16816_h(acc[mt][nt], af[mt], bf[nt]);
        }

        if (kc + 1 < NKC)
            stsA(aPtr[nxt], areg, tid);   // convert+store staged A (regs ready)
    }

    // epilogue: fused residual add, fp32 out
    const int erow = lane >> 2;
    const int ecol = (lane & 3) * 2;
    #pragma unroll
    for (int mt = 0; mt < 4; mt++) {
        int t_lo = t0 + wm * 64 + mt * 16 + erow;
        #pragma unroll
        for (int nt = 0; nt < 8; nt++) {
            int o = o0 + wn * 64 + nt * 8 + ecol;
            size_t i0 = ((size_t)t_lo * B_DIM + b) * C_DIM + o;
            size_t i1 = i0 + (size_t)8 * B_DIM * C_DIM;   // t_lo + 8
            float2 y0 = __half22float2(*(const __half2*)&acc[mt][nt][0]);
            float2 y1 = __half22float2(*(const __half2*)&acc[mt][nt][1]);
            float2 x0 = *(const float2*)(x + i0);
            float2 x1 = *(const float2*)(x + i1);
            y0.x += x0.x; y0.y += x0.y;
            y1.x += x1.x; y1.y += x1.y;
            *(float2*)(out + i0) = y0;
            *(float2*)(out + i1) = y1;
        }
    }
}

// ================================================================================
extern "C" void kernel_launch(void* const* d_in, const int* in_sizes, int n_in,
                              void* d_out, int out_size) {
    const float* x   = (const float*)d_in[0];
    const float* key = (const float*)d_in[1];
    const float* aw  = (const float*)d_in[2];
    const float* ab  = (const float*)d_in[3];
    const float* pw  = (const float*)d_in[4];
    float* out = (float*)d_out;

    cudaFuncSetAttribute(gemm_kernel, cudaFuncAttributeMaxDynamicSharedMemorySize, SMEM_BYTES);

    routing_kernel<<<B_DIM, 512>>>(key, aw, ab);
    wgen_kernel<<<1024, 256>>>((const float4*)pw, out, out_size);
    gemm_kernel<<<dim3(C_DIM / BN, T_DIM / BM, B_DIM), 256, SMEM_BYTES>>>(x, out);
}

// round 16
// speedup vs baseline: 1.0646x; 1.0064x over previous
#include <cuda_runtime.h>
#include <cuda_fp16.h>
#include <cstdint>
#include <math.h>

// Problem dims
#define T_DIM 1024
#define B_DIM 32
#define C_DIM 1024
#define K_DIM 1024
#define E_DIM 16
#define TBC   33554432  // T*B*C

// ---------------- device scratch (allocation-free rule: __device__ globals) -----
__device__ float                   g_resp[B_DIM * E_DIM];
__device__ __align__(256) __half   g_w[(size_t)B_DIM * C_DIM * C_DIM];  // 67MB

// ---------------- helpers -------------------------------------------------------
__device__ __forceinline__ uint32_t smem_u32(const void* p) {
    uint32_t a;
    asm("{ .reg .u64 t; cvta.to.shared.u64 t, %1; cvt.u32.u64 %0, t; }" : "=r"(a) : "l"(p));
    return a;
}
__device__ __forceinline__ void cp16(uint32_t dst, const void* src) {
    asm volatile("cp.async.cg.shared.global [%0], [%1], 16;" :: "r"(dst), "l"(src));
}
__device__ __forceinline__ void ldsm_x4(uint32_t* r, uint32_t addr) {
    asm volatile("ldmatrix.sync.aligned.m8n8.x4.shared.b16 {%0,%1,%2,%3}, [%4];"
                 : "=r"(r[0]), "=r"(r[1]), "=r"(r[2]), "=r"(r[3]) : "r"(addr));
}
// fp16 in, fp16 accum
__device__ __forceinline__ void mma16816_h(uint32_t* c, const uint32_t* a, const uint32_t* b) {
    asm volatile(
        "mma.sync.aligned.m16n8k16.row.col.f16.f16.f16.f16 "
        "{%0,%1}, {%2,%3,%4,%5}, {%6,%7}, {%0,%1};"
        : "+r"(c[0]), "+r"(c[1])
        : "r"(a[0]), "r"(a[1]), "r"(a[2]), "r"(a[3]), "r"(b[0]), "r"(b[1]));
}

// ================================================================================
// Kernel 1: routing — block b; thread t covers k in {t, t+512} for ALL 16 experts
//   (fully coalesced key + aw loads), butterfly + smem reduction, softmax.
// ================================================================================
__global__ void __launch_bounds__(512)
routing_kernel(const float* __restrict__ key,
               const float4* __restrict__ aw4,   // aw as float4: [K][4]
               const float* __restrict__ ab) {
    __shared__ float sred[16][E_DIM];
    __shared__ float slog[E_DIM];
    const int b = blockIdx.x;
    const int tid = threadIdx.x;
    const int lane = tid & 31, wid = tid >> 5;
    const float* kr = key + b * K_DIM;

    float acc[E_DIM];
    #pragma unroll
    for (int e = 0; e < E_DIM; e++) acc[e] = 0.f;

    #pragma unroll
    for (int rep = 0; rep < 2; rep++) {
        int k = tid + rep * 512;
        float kv = kr[k];
        #pragma unroll
        for (int q = 0; q < 4; q++) {
            float4 w = aw4[(size_t)k * 4 + q];
            acc[q * 4 + 0] = fmaf(kv, w.x, acc[q * 4 + 0]);
            acc[q * 4 + 1] = fmaf(kv, w.y, acc[q * 4 + 1]);
            acc[q * 4 + 2] = fmaf(kv, w.z, acc[q * 4 + 2]);
            acc[q * 4 + 3] = fmaf(kv, w.w, acc[q * 4 + 3]);
        }
    }
    // warp butterfly reduce (16 parallel chains)
    #pragma unroll
    for (int off = 16; off > 0; off >>= 1)
        #pragma unroll
        for (int e = 0; e < E_DIM; e++)
            acc[e] += __shfl_xor_sync(0xFFFFFFFF, acc[e], off);
    if (lane == 0)
        #pragma unroll
        for (int e = 0; e < E_DIM; e++) sred[wid][e] = acc[e];
    __syncthreads();
    if (tid < E_DIM) {
        float s = 0.f;
        #pragma unroll
        for (int w = 0; w < 16; w++) s += sred[w][tid];
        slog[tid] = s + ab[tid];
    }
    __syncthreads();
    if (tid == 0) {
        float mx = -1e30f;
        #pragma unroll
        for (int j = 0; j < E_DIM; j++) mx = fmaxf(mx, slog[j]);
        float v[E_DIM]; float s = 0.f;
        #pragma unroll
        for (int j = 0; j < E_DIM; j++) { v[j] = expf(slog[j] - mx); s += v[j]; }
        float inv = 1.f / s;
        #pragma unroll
        for (int j = 0; j < E_DIM; j++) g_resp[b * E_DIM + j] = v[j] * inv;
    }
}

// ================================================================================
// Kernel 2: W[b] = sum_e resp[b,e] * pw_w1[e] in HALF2 arithmetic (fp16 out);
//           block 0 emits the loss scalar (fp32, exact). pw read with .cs.
// ================================================================================
__global__ void __launch_bounds__(256)
wgen_kernel(const float4* __restrict__ pw,
            float* __restrict__ out, int out_size) {
    __shared__ __half2 sresp2[B_DIM * E_DIM];      // (r,r) broadcast pairs
    __shared__ float   srespf[B_DIM * E_DIM];
    for (int i = threadIdx.x; i < B_DIM * E_DIM; i += blockDim.x) {
        float r = g_resp[i];
        srespf[i] = r;
        sresp2[i] = __float2half2_rn(r);
    }
    __syncthreads();

    if (blockIdx.x == 0 && threadIdx.x == 0 && out_size > TBC) {
        float imp[E_DIM]; float tot = 0.f;
        #pragma unroll
        for (int j = 0; j < E_DIM; j++) {
            float s = 0.f;
            for (int bb = 0; bb < B_DIM; bb++) s += srespf[bb * E_DIM + j];
            imp[j] = s; tot += s;
        }
        float mean = tot / E_DIM;
        float var = 0.f;
        #pragma unroll
        for (int j = 0; j < E_DIM; j++) { float d = imp[j] - mean; var += d * d; }
        var /= (E_DIM - 1);
        out[out_size - 1] = 0.01f * sqrtf(var) / mean;
    }

    size_t n4 = (size_t)blockIdx.x * blockDim.x + threadIdx.x;  // < 262144 (= C*C/4)
    __half2 p2[2 * E_DIM];                      // pw quad as half2 pairs (32 regs)
    #pragma unroll
    for (int e = 0; e < E_DIM; e++) {
        float4 v = __ldcs(&pw[(size_t)e * 262144 + n4]);  // streaming: don't pollute L2
        p2[2 * e]     = __floats2half2_rn(v.x, v.y);
        p2[2 * e + 1] = __floats2half2_rn(v.z, v.w);
    }
    for (int b = 0; b < B_DIM; b++) {
        __half2 a0 = __float2half2_rn(0.f);
        __half2 a1 = __float2half2_rn(0.f);
        #pragma unroll
        for (int e = 0; e < E_DIM; e++) {
            __half2 r = sresp2[b * E_DIM + e];
            a0 = __hfma2(r, p2[2 * e],     a0);
            a1 = __hfma2(r, p2[2 * e + 1], a1);
        }
        union { __half2 h[2]; uint2 u; } o;
        o.h[0] = a0; o.h[1] = a1;
        ((uint2*)(g_w + (size_t)b * (C_DIM * C_DIM)))[n4] = o.u;
    }
}

// ================================================================================
// Kernel 3: batched GEMM  Y_b = X_b @ W_b^T + residual  (mma.sync fp16, fp16 acc)
//   A: fp32 LDG.128 -> regs -> cvt -> STS fp16 (double-buffered; convert hidden
//   under MMA phase). B: fp16 cp.async 2-stage. CTA 128x256, warp tile 64x64.
//   Epilogue stores use .cs (out never re-read; keep L2 for A/B tiles).
// ================================================================================
#define BM 128
#define BN 256
#define BK 32
#define PROW 80                         // 32 fp16 = 64B + 16B pad
#define NKC (C_DIM / BK)                // 32 k-chunks
#define A_STAGE (BM * PROW)             // 10240
#define B_STAGE (BN * PROW)             // 20480
#define SMEM_BYTES (2 * (A_STAGE + B_STAGE))  // 61440

__device__ __forceinline__ void issue_B(uint32_t bbuf, const __half* Bg, int ko, int tid) {
    #pragma unroll
    for (int i = 0; i < 4; i++) {
        int idx = tid + i * 256;
        int r = idx >> 2, c = idx & 3;
        cp16(bbuf + r * PROW + c * 16, Bg + (size_t)r * C_DIM + ko + c * 8);
    }
}
__device__ __forceinline__ void loadA_regs(float4* v, const float* Agf, int ko, int tid) {
    #pragma unroll
    for (int i = 0; i < 4; i++) {
        int idx = tid + i * 256;
        int r = idx >> 3, c = idx & 7;
        v[i] = *(const float4*)(Agf + (size_t)r * (B_DIM * C_DIM) + ko + c * 4);
    }
}
__device__ __forceinline__ void stsA(char* abuf, const float4* v, int tid) {
    #pragma unroll
    for (int i = 0; i < 4; i++) {
        int idx = tid + i * 256;
        int r = idx >> 3, c = idx & 7;
        union { __half h[4]; uint2 u; } o;
        o.h[0] = __float2half(v[i].x);
        o.h[1] = __float2half(v[i].y);
        o.h[2] = __float2half(v[i].z);
        o.h[3] = __float2half(v[i].w);
        *(uint2*)(abuf + r * PROW + c * 8) = o.u;
    }
}

__global__ void __launch_bounds__(256, 2)
gemm_kernel(const float* __restrict__ x, float* __restrict__ out) {
    extern __shared__ __align__(16) char smem[];

    const int tid = threadIdx.x;
    const int lane = tid & 31, wid = tid >> 5;
    const int wm = wid >> 2;          // 0..1  (64 rows each)
    const int wn = wid & 3;           // 0..3  (64 cols each)
    const int o0 = blockIdx.x * BN;
    const int t0 = blockIdx.y * BM;
    const int b  = blockIdx.z;

    const float*  Agf = x   + ((size_t)t0 * B_DIM + b) * C_DIM;      // fp32 A source
    const __half* Bg  = g_w + ((size_t)b * C_DIM + o0) * C_DIM;      // row stride C

    const uint32_t base = smem_u32(smem);
    char*    aPtr[2] = { smem, smem + A_STAGE };
    uint32_t aAdr[2] = { base, base + A_STAGE };
    uint32_t bAdr[2] = { base + 2 * A_STAGE, base + 2 * A_STAGE + B_STAGE };

    uint32_t acc[4][8][2];            // fp16x2 accumulators, warp tile 64x64
    #pragma unroll
    for (int i = 0; i < 4; i++)
        #pragma unroll
        for (int j = 0; j < 8; j++) { acc[i][j][0] = 0u; acc[i][j][1] = 0u; }

    // ldmatrix address components
    const int a_row = lane & 15;
    const int a_col = (lane >> 4) * 8;
    const int bq = lane >> 3;
    const int b_row = (bq >> 1) * 8 + (lane & 7);
    const int b_col = (bq & 1) * 8;

    // prologue: chunk 0 — A via regs, B via cp.async
    float4 areg[4];
    loadA_regs(areg, Agf, 0, tid);
    issue_B(bAdr[0], Bg, 0, tid);
    asm volatile("cp.async.commit_group;" ::: "memory");
    stsA(aPtr[0], areg, tid);

    #pragma unroll 1
    for (int kc = 0; kc < NKC; kc++) {
        const int cur = kc & 1, nxt = cur ^ 1;
        asm volatile("cp.async.wait_group 0;" ::: "memory");  // B[cur] landed
        __syncthreads();               // A16[cur] visible; prev readers done

        if (kc + 1 < NKC) {            // stage kc+1 (LDG latency hidden by MMA)
            loadA_regs(areg, Agf, (kc + 1) * BK, tid);
            issue_B(bAdr[nxt], Bg, (kc + 1) * BK, tid);
            asm volatile("cp.async.commit_group;" ::: "memory");
        }

        const uint32_t Ab = aAdr[cur] + (uint32_t)(wm * 64) * PROW;
        const uint32_t Bb = bAdr[cur] + (uint32_t)(wn * 64) * PROW;

        #pragma unroll
        for (int ks = 0; ks < 2; ks++) {
            uint32_t af[4][4];
            #pragma unroll
            for (int mt = 0; mt < 4; mt++)
                ldsm_x4(af[mt], Ab + (uint32_t)(mt * 16 + a_row) * PROW + (a_col + ks * 16) * 2);
            uint32_t bf[8][2];
            #pragma unroll
            for (int nt2 = 0; nt2 < 4; nt2++) {
                uint32_t t4[4];
                ldsm_x4(t4, Bb + (uint32_t)(nt2 * 16 + b_row) * PROW + (b_col + ks * 16) * 2);
                bf[nt2 * 2][0] = t4[0]; bf[nt2 * 2][1] = t4[1];
                bf[nt2 * 2 + 1][0] = t4[2]; bf[nt2 * 2 + 1][1] = t4[3];
            }
            #pragma unroll
            for (int mt = 0; mt < 4; mt++)
                #pragma unroll
                for (int nt = 0; nt < 8; nt++)
                    mma16816_h(acc[mt][nt], af[mt], bf[nt]);
        }

        if (kc + 1 < NKC)
            stsA(aPtr[nxt], areg, tid);   // convert+store staged A (regs ready)
    }

    // epilogue: fused residual add, fp32 out (streaming stores)
    const int erow = lane >> 2;
    const int ecol = (lane & 3) * 2;
    #pragma unroll
    for (int mt = 0; mt < 4; mt++) {
        int t_lo = t0 + wm * 64 + mt * 16 + erow;
        #pragma unroll
        for (int nt = 0; nt < 8; nt++) {
            int o = o0 + wn * 64 + nt * 8 + ecol;
            size_t i0 = ((size_t)t_lo * B_DIM + b) * C_DIM + o;
            size_t i1 = i0 + (size_t)8 * B_DIM * C_DIM;   // t_lo + 8
            float2 y0 = __half22float2(*(const __half2*)&acc[mt][nt][0]);
            float2 y1 = __half22float2(*(const __half2*)&acc[mt][nt][1]);
            float2 x0 = *(const float2*)(x + i0);
            float2 x1 = *(const float2*)(x + i1);
            y0.x += x0.x; y0.y += x0.y;
            y1.x += x1.x; y1.y += x1.y;
            __stcs((float2*)(out + i0), y0);
            __stcs((float2*)(out + i1), y1);
        }
    }
}

// ================================================================================
extern "C" void kernel_launch(void* const* d_in, const int* in_sizes, int n_in,
                              void* d_out, int out_size) {
    const float* x   = (const float*)d_in[0];
    const float* key = (const float*)d_in[1];
    const float* aw  = (const float*)d_in[2];
    const float* ab  = (const float*)d_in[3];
    const float* pw  = (const float*)d_in[4];
    float* out = (float*)d_out;

    cudaFuncSetAttribute(gemm_kernel, cudaFuncAttributeMaxDynamicSharedMemorySize, SMEM_BYTES);

    routing_kernel<<<B_DIM, 512>>>(key, (const float4*)aw, ab);
    wgen_kernel<<<1024, 256>>>((const float4*)pw, out, out_size);
    gemm_kernel<<<dim3(C_DIM / BN, T_DIM / BM, B_DIM), 256, SMEM_BYTES>>>(x, out);
}

// round 17
// speedup vs baseline: 1.0765x; 1.0112x over previous
#include <cuda_runtime.h>
#include <cuda_fp16.h>
#include <cstdint>
#include <math.h>

// Problem dims
#define T_DIM 1024
#define B_DIM 32
#define C_DIM 1024
#define K_DIM 1024
#define E_DIM 16
#define TBC   33554432  // T*B*C

// ---------------- device scratch (allocation-free rule: __device__ globals) -----
__device__ float                   g_resp[B_DIM * E_DIM];
__device__ __align__(256) __half   g_w[(size_t)B_DIM * C_DIM * C_DIM];  // 67MB

// ---------------- helpers -------------------------------------------------------
__device__ __forceinline__ uint32_t smem_u32(const void* p) {
    uint32_t a;
    asm("{ .reg .u64 t; cvta.to.shared.u64 t, %1; cvt.u32.u64 %0, t; }" : "=r"(a) : "l"(p));
    return a;
}
__device__ __forceinline__ void cp16(uint32_t dst, const void* src) {
    asm volatile("cp.async.cg.shared.global [%0], [%1], 16;" :: "r"(dst), "l"(src));
}
__device__ __forceinline__ void ldsm_x4(uint32_t* r, uint32_t addr) {
    asm volatile("ldmatrix.sync.aligned.m8n8.x4.shared.b16 {%0,%1,%2,%3}, [%4];"
                 : "=r"(r[0]), "=r"(r[1]), "=r"(r[2]), "=r"(r[3]) : "r"(addr));
}
// fp16 in, fp16 accum
__device__ __forceinline__ void mma16816_h(uint32_t* c, const uint32_t* a, const uint32_t* b) {
    asm volatile(
        "mma.sync.aligned.m16n8k16.row.col.f16.f16.f16.f16 "
        "{%0,%1}, {%2,%3,%4,%5}, {%6,%7}, {%0,%1};"
        : "+r"(c[0]), "+r"(c[1])
        : "r"(a[0]), "r"(a[1]), "r"(a[2]), "r"(a[3]), "r"(b[0]), "r"(b[1]));
}

// ================================================================================
// Kernel 1: routing — block b; thread t covers k in {t, t+512} for ALL 16 experts
// ================================================================================
__global__ void __launch_bounds__(512)
routing_kernel(const float* __restrict__ key,
               const float4* __restrict__ aw4,   // aw as float4: [K][4]
               const float* __restrict__ ab) {
    __shared__ float sred[16][E_DIM];
    __shared__ float slog[E_DIM];
    const int b = blockIdx.x;
    const int tid = threadIdx.x;
    const int lane = tid & 31, wid = tid >> 5;
    const float* kr = key + b * K_DIM;

    float acc[E_DIM];
    #pragma unroll
    for (int e = 0; e < E_DIM; e++) acc[e] = 0.f;

    #pragma unroll
    for (int rep = 0; rep < 2; rep++) {
        int k = tid + rep * 512;
        float kv = kr[k];
        #pragma unroll
        for (int q = 0; q < 4; q++) {
            float4 w = aw4[(size_t)k * 4 + q];
            acc[q * 4 + 0] = fmaf(kv, w.x, acc[q * 4 + 0]);
            acc[q * 4 + 1] = fmaf(kv, w.y, acc[q * 4 + 1]);
            acc[q * 4 + 2] = fmaf(kv, w.z, acc[q * 4 + 2]);
            acc[q * 4 + 3] = fmaf(kv, w.w, acc[q * 4 + 3]);
        }
    }
    #pragma unroll
    for (int off = 16; off > 0; off >>= 1)
        #pragma unroll
        for (int e = 0; e < E_DIM; e++)
            acc[e] += __shfl_xor_sync(0xFFFFFFFF, acc[e], off);
    if (lane == 0)
        #pragma unroll
        for (int e = 0; e < E_DIM; e++) sred[wid][e] = acc[e];
    __syncthreads();
    if (tid < E_DIM) {
        float s = 0.f;
        #pragma unroll
        for (int w = 0; w < 16; w++) s += sred[w][tid];
        slog[tid] = s + ab[tid];
    }
    __syncthreads();
    if (tid == 0) {
        float mx = -1e30f;
        #pragma unroll
        for (int j = 0; j < E_DIM; j++) mx = fmaxf(mx, slog[j]);
        float v[E_DIM]; float s = 0.f;
        #pragma unroll
        for (int j = 0; j < E_DIM; j++) { v[j] = expf(slog[j] - mx); s += v[j]; }
        float inv = 1.f / s;
        #pragma unroll
        for (int j = 0; j < E_DIM; j++) g_resp[b * E_DIM + j] = v[j] * inv;
    }
    cudaTriggerProgrammaticLaunchCompletion();
}

// ================================================================================
// Kernel 2 (PDL): pw loads issued BEFORE the grid-dependency wait (hides routing
// tail + launch); then resp read, loss, half2 mix.
// ================================================================================
__global__ void __launch_bounds__(256)
wgen_kernel(const float4* __restrict__ pw,
            float* __restrict__ out, int out_size) {
    __shared__ __half2 sresp2[B_DIM * E_DIM];
    __shared__ float   srespf[B_DIM * E_DIM];

    // pw loads first — independent of routing's output
    size_t n4 = (size_t)blockIdx.x * blockDim.x + threadIdx.x;  // < 262144
    float4 v[E_DIM];
    #pragma unroll
    for (int e = 0; e < E_DIM; e++)
        v[e] = __ldcs(&pw[(size_t)e * 262144 + n4]);

    cudaGridDependencySynchronize();   // routing's g_resp now visible

    for (int i = threadIdx.x; i < B_DIM * E_DIM; i += blockDim.x) {
        float r = g_resp[i];
        srespf[i] = r;
        sresp2[i] = __float2half2_rn(r);
    }
    __syncthreads();

    if (blockIdx.x == 0 && threadIdx.x == 0 && out_size > TBC) {
        float imp[E_DIM]; float tot = 0.f;
        #pragma unroll
        for (int j = 0; j < E_DIM; j++) {
            float s = 0.f;
            for (int bb = 0; bb < B_DIM; bb++) s += srespf[bb * E_DIM + j];
            imp[j] = s; tot += s;
        }
        float mean = tot / E_DIM;
        float var = 0.f;
        #pragma unroll
        for (int j = 0; j < E_DIM; j++) { float d = imp[j] - mean; var += d * d; }
        var /= (E_DIM - 1);
        out[out_size - 1] = 0.01f * sqrtf(var) / mean;
    }

    __half2 p2[2 * E_DIM];
    #pragma unroll
    for (int e = 0; e < E_DIM; e++) {
        p2[2 * e]     = __floats2half2_rn(v[e].x, v[e].y);
        p2[2 * e + 1] = __floats2half2_rn(v[e].z, v[e].w);
    }
    for (int b = 0; b < B_DIM; b++) {
        __half2 a0 = __float2half2_rn(0.f);
        __half2 a1 = __float2half2_rn(0.f);
        #pragma unroll
        for (int e = 0; e < E_DIM; e++) {
            __half2 r = sresp2[b * E_DIM + e];
            a0 = __hfma2(r, p2[2 * e],     a0);
            a1 = __hfma2(r, p2[2 * e + 1], a1);
        }
        union { __half2 h[2]; uint2 u; } o;
        o.h[0] = a0; o.h[1] = a1;
        ((uint2*)(g_w + (size_t)b * (C_DIM * C_DIM)))[n4] = o.u;
    }
    cudaTriggerProgrammaticLaunchCompletion();
}

// ================================================================================
// Kernel 3 (PDL): batched GEMM  Y_b = X_b @ W_b^T + residual (fp16 mma, fp16 acc)
//   A chunk-0 staged (x only) BEFORE the grid-dependency wait; B loads after.
// ================================================================================
#define BM 128
#define BN 256
#define BK 32
#define PROW 80                         // 32 fp16 = 64B + 16B pad
#define NKC (C_DIM / BK)                // 32 k-chunks
#define A_STAGE (BM * PROW)             // 10240
#define B_STAGE (BN * PROW)             // 20480
#define SMEM_BYTES (2 * (A_STAGE + B_STAGE))  // 61440

__device__ __forceinline__ void issue_B(uint32_t bbuf, const __half* Bg, int ko, int tid) {
    #pragma unroll
    for (int i = 0; i < 4; i++) {
        int idx = tid + i * 256;
        int r = idx >> 2, c = idx & 3;
        cp16(bbuf + r * PROW + c * 16, Bg + (size_t)r * C_DIM + ko + c * 8);
    }
}
__device__ __forceinline__ void loadA_regs(float4* v, const float* Agf, int ko, int tid) {
    #pragma unroll
    for (int i = 0; i < 4; i++) {
        int idx = tid + i * 256;
        int r = idx >> 3, c = idx & 7;
        v[i] = *(const float4*)(Agf + (size_t)r * (B_DIM * C_DIM) + ko + c * 4);
    }
}
__device__ __forceinline__ void stsA(char* abuf, const float4* v, int tid) {
    #pragma unroll
    for (int i = 0; i < 4; i++) {
        int idx = tid + i * 256;
        int r = idx >> 3, c = idx & 7;
        union { __half h[4]; uint2 u; } o;
        o.h[0] = __float2half(v[i].x);
        o.h[1] = __float2half(v[i].y);
        o.h[2] = __float2half(v[i].z);
        o.h[3] = __float2half(v[i].w);
        *(uint2*)(abuf + r * PROW + c * 8) = o.u;
    }
}

__global__ void __launch_bounds__(256, 2)
gemm_kernel(const float* __restrict__ x, float* __restrict__ out) {
    extern __shared__ __align__(16) char smem[];

    const int tid = threadIdx.x;
    const int lane = tid & 31, wid = tid >> 5;
    const int wm = wid >> 2;          // 0..1  (64 rows each)
    const int wn = wid & 3;           // 0..3  (64 cols each)
    const int o0 = blockIdx.x * BN;
    const int t0 = blockIdx.y * BM;
    const int b  = blockIdx.z;

    const float*  Agf = x   + ((size_t)t0 * B_DIM + b) * C_DIM;      // fp32 A source
    const __half* Bg  = g_w + ((size_t)b * C_DIM + o0) * C_DIM;      // row stride C

    const uint32_t base = smem_u32(smem);
    char*    aPtr[2] = { smem, smem + A_STAGE };
    uint32_t aAdr[2] = { base, base + A_STAGE };
    uint32_t bAdr[2] = { base + 2 * A_STAGE, base + 2 * A_STAGE + B_STAGE };

    uint32_t acc[4][8][2];            // fp16x2 accumulators, warp tile 64x64
    #pragma unroll
    for (int i = 0; i < 4; i++)
        #pragma unroll
        for (int j = 0; j < 8; j++) { acc[i][j][0] = 0u; acc[i][j][1] = 0u; }

    // ldmatrix address components
    const int a_row = lane & 15;
    const int a_col = (lane >> 4) * 8;
    const int bq = lane >> 3;
    const int b_row = (bq >> 1) * 8 + (lane & 7);
    const int b_col = (bq & 1) * 8;

    // prologue: A chunk 0 (depends only on x) BEFORE the dependency wait
    float4 areg[4];
    loadA_regs(areg, Agf, 0, tid);
    stsA(aPtr[0], areg, tid);

    cudaGridDependencySynchronize();   // wgen's g_w now visible

    issue_B(bAdr[0], Bg, 0, tid);
    asm volatile("cp.async.commit_group;" ::: "memory");

    #pragma unroll 1
    for (int kc = 0; kc < NKC; kc++) {
        const int cur = kc & 1, nxt = cur ^ 1;
        asm volatile("cp.async.wait_group 0;" ::: "memory");  // B[cur] landed
        __syncthreads();               // A16[cur] visible; prev readers done

        if (kc + 1 < NKC) {            // stage kc+1 (LDG latency hidden by MMA)
            loadA_regs(areg, Agf, (kc + 1) * BK, tid);
            issue_B(bAdr[nxt], Bg, (kc + 1) * BK, tid);
            asm volatile("cp.async.commit_group;" ::: "memory");
        }

        const uint32_t Ab = aAdr[cur] + (uint32_t)(wm * 64) * PROW;
        const uint32_t Bb = bAdr[cur] + (uint32_t)(wn * 64) * PROW;

        #pragma unroll
        for (int ks = 0; ks < 2; ks++) {
            uint32_t af[4][4];
            #pragma unroll
            for (int mt = 0; mt < 4; mt++)
                ldsm_x4(af[mt], Ab + (uint32_t)(mt * 16 + a_row) * PROW + (a_col + ks * 16) * 2);
            uint32_t bf[8][2];
            #pragma unroll
            for (int nt2 = 0; nt2 < 4; nt2++) {
                uint32_t t4[4];
                ldsm_x4(t4, Bb + (uint32_t)(nt2 * 16 + b_row) * PROW + (b_col + ks * 16) * 2);
                bf[nt2 * 2][0] = t4[0]; bf[nt2 * 2][1] = t4[1];
                bf[nt2 * 2 + 1][0] = t4[2]; bf[nt2 * 2 + 1][1] = t4[3];
            }
            #pragma unroll
            for (int mt = 0; mt < 4; mt++)
                #pragma unroll
                for (int nt = 0; nt < 8; nt++)
                    mma16816_h(acc[mt][nt], af[mt], bf[nt]);
        }

        if (kc + 1 < NKC)
            stsA(aPtr[nxt], areg, tid);   // convert+store staged A (regs ready)
    }

    // epilogue: fused residual add, fp32 out (streaming stores)
    const int erow = lane >> 2;
    const int ecol = (lane & 3) * 2;
    #pragma unroll
    for (int mt = 0; mt < 4; mt++) {
        int t_lo = t0 + wm * 64 + mt * 16 + erow;
        #pragma unroll
        for (int nt = 0; nt < 8; nt++) {
            int o = o0 + wn * 64 + nt * 8 + ecol;
            size_t i0 = ((size_t)t_lo * B_DIM + b) * C_DIM + o;
            size_t i1 = i0 + (size_t)8 * B_DIM * C_DIM;   // t_lo + 8
            float2 y0 = __half22float2(*(const __half2*)&acc[mt][nt][0]);
            float2 y1 = __half22float2(*(const __half2*)&acc[mt][nt][1]);
            float2 x0 = *(const float2*)(x + i0);
            float2 x1 = *(const float2*)(x + i1);
            y0.x += x0.x; y0.y += x0.y;
            y1.x += x1.x; y1.y += x1.y;
            __stcs((float2*)(out + i0), y0);
            __stcs((float2*)(out + i1), y1);
        }
    }
}

// ================================================================================
extern "C" void kernel_launch(void* const* d_in, const int* in_sizes, int n_in,
                              void* d_out, int out_size) {
    const float* x   = (const float*)d_in[0];
    const float* key = (const float*)d_in[1];
    const float* aw  = (const float*)d_in[2];
    const float* ab  = (const float*)d_in[3];
    const float* pw  = (const float*)d_in[4];
    float* out = (float*)d_out;

    cudaFuncSetAttribute(gemm_kernel, cudaFuncAttributeMaxDynamicSharedMemorySize, SMEM_BYTES);

    routing_kernel<<<B_DIM, 512>>>(key, (const float4*)aw, ab);

    cudaLaunchAttribute pdl[1];
    pdl[0].id = cudaLaunchAttributeProgrammaticStreamSerialization;
    pdl[0].val.programmaticStreamSerializationAllowed = 1;

    {   // wgen with PDL
        cudaLaunchConfig_t cfg = {};
        cfg.gridDim = dim3(1024, 1, 1);
        cfg.blockDim = dim3(256, 1, 1);
        cfg.attrs = pdl;
        cfg.numAttrs = 1;
        cudaLaunchKernelEx(&cfg, wgen_kernel, (const float4*)pw, out, out_size);
    }
    {   // gemm with PDL
        cudaLaunchConfig_t cfg = {};
        cfg.gridDim = dim3(C_DIM / BN, T_DIM / BM, B_DIM);
        cfg.blockDim = dim3(256, 1, 1);
        cfg.dynamicSmemBytes = SMEM_BYTES;
        cfg.attrs = pdl;
        cfg.numAttrs = 1;
        cudaLaunchKernelEx(&cfg, gemm_kernel, x, out);
    }
}